// round 1
// baseline (speedup 1.0000x reference)
#include <cuda_runtime.h>
#include <cuda_bf16.h>

// Output[b,s,:] == mean(knowledge, axis=0) for every (b,s):
// top_k with max_chunks == K selects a permutation of ALL knowledge rows,
// and the mean over a permutation equals the mean over the rows.
//
// Kernel 1: compute the 512-element mean of knowledge[64,512] (one block).
// Kernel 2: broadcast that 2KB vector to all 4096 output rows (8MB write).

#define E_DIM 512
#define K_ROWS 64
#define BCAST_BLOCKS 512
#define BCAST_THREADS 128   // 128 threads * float4 = 512 floats = one row

// Device-global scratch (no allocation allowed in kernel_launch).
__device__ float g_mean[E_DIM];

__global__ void knowledge_mean_kernel(const float* __restrict__ knowledge) {
    int t = threadIdx.x;  // 512 threads, one per embedding dim
    float s = 0.0f;
#pragma unroll
    for (int k = 0; k < K_ROWS; ++k) {
        s += knowledge[k * E_DIM + t];
    }
    g_mean[t] = s * (1.0f / (float)K_ROWS);
}

__global__ void __launch_bounds__(BCAST_THREADS)
broadcast_kernel(float4* __restrict__ out, int rows) {
    int t = threadIdx.x;  // 0..127, each owns one float4 column of the row
    float4 v = reinterpret_cast<const float4*>(g_mean)[t];

    // Contiguous chunk of rows per block.
    int rows_per_block = (rows + gridDim.x - 1) / gridDim.x;
    int r0 = blockIdx.x * rows_per_block;
    int r1 = min(r0 + rows_per_block, rows);
    for (int r = r0; r < r1; ++r) {
        out[(size_t)r * (E_DIM / 4) + t] = v;
    }
}

extern "C" void kernel_launch(void* const* d_in, const int* in_sizes, int n_in,
                              void* d_out, int out_size) {
    // d_in[0]: query_embedding [4,1024,512] f32 (unused — output is query-independent)
    // d_in[1]: knowledge [64,512] f32
    const float* knowledge = (const float*)d_in[1];
    float* out = (float*)d_out;

    int rows = out_size / E_DIM;  // 4096

    knowledge_mean_kernel<<<1, E_DIM>>>(knowledge);
    broadcast_kernel<<<BCAST_BLOCKS, BCAST_THREADS>>>(
        reinterpret_cast<float4*>(out), rows);
}

// round 2
// speedup vs baseline: 1.0295x; 1.0295x over previous
#include <cuda_runtime.h>
#include <cuda_bf16.h>
#include <cstdint>

// Output[b,s,:] == mean(knowledge, axis=0) for every (b,s):
// top_k with max_chunks == K selects a permutation of ALL knowledge rows,
// so mean(take(knowledge, top_k), axis=1) == mean(knowledge, axis=0).
//
// Kernel 1: mean of knowledge[64,512] -> g_mean (one block).
// Kernel 2: broadcast via TMA bulk stores. Each CTA fills a 32KB smem tile
//           (16 replicated rows) and issues two 32KB cp.async.bulk stores,
//           bypassing the STG.128 issue floor (12 cyc/SMSP) that bound R1.

#define E_DIM 512
#define K_ROWS 64
#define ROWS_PER_TILE 16               // 16 rows * 2KB = 32KB smem tile
#define ROWS_PER_CTA 32                // two bulk stores per CTA
#define TILE_BYTES (ROWS_PER_TILE * E_DIM * 4)  // 32768

__device__ float g_mean[E_DIM];

__global__ void knowledge_mean_kernel(const float* __restrict__ knowledge) {
    int t = threadIdx.x;  // 512 threads, one per embedding dim
    float s = 0.0f;
#pragma unroll
    for (int k = 0; k < K_ROWS; ++k) {
        s += knowledge[k * E_DIM + t];
    }
    g_mean[t] = s * (1.0f / (float)K_ROWS);
}

__global__ void __launch_bounds__(128)
broadcast_tma_kernel(float4* __restrict__ out) {
    __shared__ __align__(128) float4 tile[ROWS_PER_TILE * 128];

    int t = threadIdx.x;  // 0..127, one float4 column per thread
    float4 v = reinterpret_cast<const float4*>(g_mean)[t];

    // Replicate the 2KB row pattern 16x into the smem tile.
#pragma unroll
    for (int r = 0; r < ROWS_PER_TILE; ++r) {
        tile[r * 128 + t] = v;
    }

    // Make generic-proxy smem writes visible to the async (TMA) proxy.
    asm volatile("fence.proxy.async.shared::cta;" ::: "memory");
    __syncthreads();

    if (t == 0) {
        uint32_t s_addr = (uint32_t)__cvta_generic_to_shared(tile);
        size_t base = (size_t)blockIdx.x * ROWS_PER_CTA * (E_DIM / 4);
        float4* g0 = out + base;
        float4* g1 = out + base + ROWS_PER_TILE * (E_DIM / 4);
        unsigned bytes = TILE_BYTES;
        asm volatile(
            "cp.async.bulk.global.shared::cta.bulk_group [%0], [%1], %2;"
            :: "l"(g0), "r"(s_addr), "r"(bytes) : "memory");
        asm volatile(
            "cp.async.bulk.global.shared::cta.bulk_group [%0], [%1], %2;"
            :: "l"(g1), "r"(s_addr), "r"(bytes) : "memory");
        asm volatile("cp.async.bulk.commit_group;" ::: "memory");
        asm volatile("cp.async.bulk.wait_group 0;" ::: "memory");
    }
}

extern "C" void kernel_launch(void* const* d_in, const int* in_sizes, int n_in,
                              void* d_out, int out_size) {
    // d_in[0]: query_embedding [4,1024,512] f32 (unused — output is query-independent)
    // d_in[1]: knowledge [64,512] f32
    const float* knowledge = (const float*)d_in[1];
    float* out = (float*)d_out;

    int rows = out_size / E_DIM;              // 4096
    int blocks = rows / ROWS_PER_CTA;         // 128

    knowledge_mean_kernel<<<1, E_DIM>>>(knowledge);
    broadcast_tma_kernel<<<blocks, 128>>>(reinterpret_cast<float4*>(out));
}